// round 15
// baseline (speedup 1.0000x reference)
#include <cuda_runtime.h>
#include <cuda_bf16.h>
#include <cstdint>

// Problem constants
#define Bsz 32
#define Tlen 1024
#define Idim 512
#define Hdim 512

// Scratch (device globals: no allocation allowed)
__device__ float g_xproj[(size_t)Bsz * Tlen * Hdim];                  // 64 MB
__device__ __align__(16) __nv_bfloat16 g_xh[(size_t)Bsz * Tlen * Idim];
__device__ __align__(16) __nv_bfloat16 g_xl[(size_t)Bsz * Tlen * Idim];
__device__ __align__(16) __nv_bfloat16 g_wh[(size_t)Hdim * Idim];
__device__ __align__(16) __nv_bfloat16 g_wl[(size_t)Hdim * Idim];

// ---------------------------------------------------------------------------
// packed f32x2 helpers (FFMA2 — ptxas never auto-fuses; PTX-only)
// ---------------------------------------------------------------------------
using u64 = unsigned long long;
__device__ __forceinline__ u64 pk2(float lo, float hi) {
    u64 r; asm("mov.b64 %0,{%1,%2};" : "=l"(r) : "f"(lo), "f"(hi)); return r;
}
__device__ __forceinline__ float2 upk2(u64 v) {
    float2 f; asm("mov.b64 {%0,%1},%2;" : "=f"(f.x), "=f"(f.y) : "l"(v)); return f;
}
__device__ __forceinline__ u64 fma2(u64 a, u64 b, u64 c) {
    u64 d; asm("fma.rn.f32x2 %0,%1,%2,%3;" : "=l"(d) : "l"(a), "l"(b), "l"(c)); return d;
}
__device__ __forceinline__ u64 add2(u64 a, u64 b) {
    u64 d; asm("add.rn.f32x2 %0,%1,%2;" : "=l"(d) : "l"(a), "l"(b)); return d;
}
__device__ __forceinline__ u64 mul2(u64 a, u64 b) {
    u64 d; asm("mul.rn.f32x2 %0,%1,%2;" : "=l"(d) : "l"(a), "l"(b)); return d;
}

__device__ __forceinline__ uint32_t s2u(const void* p) {
    uint32_t a;
    asm("{ .reg .u64 t; cvta.to.shared.u64 t, %1; cvt.u32.u64 %0, t; }"
        : "=r"(a) : "l"(p));
    return a;
}
__device__ __forceinline__ uint32_t mapa_rank(uint32_t laddr, uint32_t rank) {
    uint32_t r;
    asm("mapa.shared::cluster.u32 %0, %1, %2;" : "=r"(r) : "r"(laddr), "r"(rank));
    return r;
}
__device__ __forceinline__ void mbar_init(uint32_t mb, uint32_t cnt) {
    asm volatile("mbarrier.init.shared.b64 [%0], %1;" :: "r"(mb), "r"(cnt) : "memory");
}
__device__ __forceinline__ void mbar_arrive_expect_tx(uint32_t mb, uint32_t bytes) {
    asm volatile("mbarrier.arrive.expect_tx.shared.b64 _, [%0], %1;"
                 :: "r"(mb), "r"(bytes) : "memory");
}
__device__ __forceinline__ void mbar_wait_parity(uint32_t mb, uint32_t parity) {
    asm volatile(
        "{\n\t"
        ".reg .pred P;\n\t"
        "WLOOP_%=:\n\t"
        "mbarrier.try_wait.parity.acquire.cta.shared::cta.b64 P, [%0], %1, 0x989680;\n\t"
        "@P bra.uni WDONE_%=;\n\t"
        "bra.uni WLOOP_%=;\n\t"
        "WDONE_%=:\n\t"
        "}"
        :: "r"(mb), "r"(parity) : "memory");
}
__device__ __forceinline__ void bulk_dsmem(uint32_t dst, uint32_t src,
                                           uint32_t bytes, uint32_t rembar) {
    asm volatile(
        "cp.async.bulk.shared::cluster.shared::cta.mbarrier::complete_tx::bytes "
        "[%0], [%1], %2, [%3];"
        :: "r"(dst), "r"(src), "r"(bytes), "r"(rembar) : "memory");
}
__device__ __forceinline__ void fence_proxy_async_cta() {
    asm volatile("fence.proxy.async.shared::cta;" ::: "memory");
}
__device__ __forceinline__ void cluster_sync_asm() {
    asm volatile("barrier.cluster.arrive.aligned;" ::: "memory");
    asm volatile("barrier.cluster.wait.aligned;" ::: "memory");
}
__device__ __forceinline__ u64 shflx2(u64 v, int m) {
    float2 f = upk2(v);
    f.x = __shfl_xor_sync(0xFFFFFFFFu, f.x, m);
    f.y = __shfl_xor_sync(0xFFFFFFFFu, f.y, m);
    return pk2(f.x, f.y);
}
// Fast branch-free tanh (rel err ~1e-6, fine vs 1e-3 tolerance)
__device__ __forceinline__ float ftanh(float x) {
    float ax = fabsf(x);
    float e = __expf(-2.0f * ax);
    float r = __fdividef(1.0f - e, 1.0f + e);
    return copysignf(r, x);
}

// ---------------------------------------------------------------------------
// Kernel 0: split fp32 -> (bf16 hi, bf16 lo). One launch covers X then Wih.
// ---------------------------------------------------------------------------
__global__ void split_bf16_kernel(const float* __restrict__ x,
                                  const float* __restrict__ wih,
                                  int nx4, int ntot4)
{
    int i = blockIdx.x * blockDim.x + threadIdx.x;
    if (i >= ntot4) return;
    const float* src;
    __nv_bfloat16 *hi, *lo;
    int j;
    if (i < nx4) { src = x;   hi = g_xh; lo = g_xl; j = i; }
    else         { src = wih; hi = g_wh; lo = g_wl; j = i - nx4; }
    float4 v = ((const float4*)src)[j];
    __nv_bfloat16 h0 = __float2bfloat16(v.x);
    __nv_bfloat16 h1 = __float2bfloat16(v.y);
    __nv_bfloat16 h2 = __float2bfloat16(v.z);
    __nv_bfloat16 h3 = __float2bfloat16(v.w);
    __nv_bfloat16 l0 = __float2bfloat16(v.x - __bfloat162float(h0));
    __nv_bfloat16 l1 = __float2bfloat16(v.y - __bfloat162float(h1));
    __nv_bfloat16 l2 = __float2bfloat16(v.z - __bfloat162float(h2));
    __nv_bfloat16 l3 = __float2bfloat16(v.w - __bfloat162float(h3));
    __nv_bfloat162* hp = (__nv_bfloat162*)(hi + 4 * (size_t)j);
    __nv_bfloat162* lp = (__nv_bfloat162*)(lo + 4 * (size_t)j);
    hp[0] = __halves2bfloat162(h0, h1);
    hp[1] = __halves2bfloat162(h2, h3);
    lp[0] = __halves2bfloat162(l0, l1);
    lp[1] = __halves2bfloat162(l2, l3);
}

// ---------------------------------------------------------------------------
// Kernel 1: xproj via mma.sync.m16n8k16.bf16 (split-bf16, 3-product fp32
//   emulation; HMMA — tcgen05 unavailable through compute_103 PTX).
//   CTA tile 128m x 128n, K chunked by 64, cp.async double-buffered smem.
//   Fragments loaded via ldmatrix.m8n8.x4 (pad-144 rows -> banks 4r mod 32,
//   conflict-free): 48 ldmatrix per warp-chunk instead of 192 LDS.32.
// ---------------------------------------------------------------------------
#define MMA_BF16(d, a, b0_, b1_) \
    asm volatile( \
        "mma.sync.aligned.m16n8k16.row.col.f32.bf16.bf16.f32 " \
        "{%0,%1,%2,%3}, {%4,%5,%6,%7}, {%8,%9}, {%0,%1,%2,%3};" \
        : "+f"((d)[0]), "+f"((d)[1]), "+f"((d)[2]), "+f"((d)[3]) \
        : "r"((a)[0]), "r"((a)[1]), "r"((a)[2]), "r"((a)[3]), \
          "r"(b0_), "r"(b1_))

#define LDMX4(r, addr) \
    asm volatile("ldmatrix.sync.aligned.m8n8.x4.shared.b16 {%0,%1,%2,%3}, [%4];" \
        : "=r"((r)[0]), "=r"((r)[1]), "=r"((r)[2]), "=r"((r)[3]) : "r"(addr))

static constexpr int XPADB = 144;                   // 72 bf16 per row, bytes
static constexpr int MAT_BYTES = 128 * XPADB;       // 18432
static constexpr int BUF_BYTES = 4 * MAT_BYTES;     // 73728
static constexpr int XS_TOTAL  = 2 * BUF_BYTES;     // 147456

__global__ void __launch_bounds__(256, 1)
xproj_mma_kernel(const float* __restrict__ bih, const float* __restrict__ bhh)
{
    extern __shared__ __align__(128) char xsm[];
    const int tid  = threadIdx.x;
    const int lane = tid & 31;
    const int w    = tid >> 5;
    const int wm   = w >> 2;          // 0..1 (m 64-block)
    const int wn   = w & 3;           // 0..3 (n 32-block)
    const int m0 = blockIdx.y * 128;
    const int h0 = blockIdx.x * 128;
    const uint32_t sb = s2u(xsm);

    const int lr = lane >> 2;         // fragment row 0..7
    const int lc = (lane & 3) * 2;    // fragment col pair base

    // ldmatrix per-lane addressing (row part constant per lane)
    const int laneA_row  = (lane & 7) + ((lane >> 3) & 1) * 8;  // 0..15
    const int laneA_koff = (lane >> 4) * 16;                     // 0/16 bytes
    const int laneB_row  = ((lane >> 4) & 1) * 8 + (lane & 7);  // nt-local row
    const int laneB_koff = ((lane >> 3) & 1) * 16;

    auto issue_chunk = [&](int buf, int k0) {
#pragma unroll
        for (int q = 0; q < 16; ++q) {
            int idx = tid + 256 * q;
            int mat = idx >> 10;          // 0=xh 1=xl 2=wh 3=wl
            int it  = idx & 1023;
            int r   = it >> 3;
            int c8  = (it & 7) * 8;
            const __nv_bfloat16* src;
            if (mat == 0)      src = g_xh + (size_t)(m0 + r) * Idim + k0 + c8;
            else if (mat == 1) src = g_xl + (size_t)(m0 + r) * Idim + k0 + c8;
            else if (mat == 2) src = g_wh + (size_t)(h0 + r) * Idim + k0 + c8;
            else               src = g_wl + (size_t)(h0 + r) * Idim + k0 + c8;
            uint32_t dst = sb + (uint32_t)(buf * BUF_BYTES + mat * MAT_BYTES
                                           + r * XPADB + c8 * 2);
            asm volatile("cp.async.cg.shared.global [%0], [%1], 16;"
                         :: "r"(dst), "l"(src));
        }
        asm volatile("cp.async.commit_group;" ::: "memory");
    };

    issue_chunk(0, 0);

    float acc[4][4][4];
#pragma unroll
    for (int i = 0; i < 4; ++i)
#pragma unroll
        for (int j = 0; j < 4; ++j)
#pragma unroll
            for (int v = 0; v < 4; ++v) acc[i][j][v] = 0.f;

    asm volatile("cp.async.wait_group 0;" ::: "memory");
    __syncthreads();

    for (int ch = 0; ch < 8; ++ch) {
        const int buf = ch & 1;
        if (ch < 7) issue_chunk(buf ^ 1, (ch + 1) * 64);

        const uint32_t A0 = sb + buf * BUF_BYTES;      // xh
        const uint32_t A1 = A0 + MAT_BYTES;            // xl
        const uint32_t B0 = A0 + 2 * MAT_BYTES;        // wh
        const uint32_t B1 = A0 + 3 * MAT_BYTES;        // wl

#pragma unroll
        for (int kk = 0; kk < 4; ++kk) {
            const int kb = kk * 32;                    // 16 bf16 = 32 bytes
            uint32_t aH[4][4], aL[4][4];
#pragma unroll
            for (int mt = 0; mt < 4; ++mt) {
                const uint32_t ro = (uint32_t)((wm * 64 + mt * 16 + laneA_row) * XPADB
                                               + kb + laneA_koff);
                LDMX4(aH[mt], A0 + ro);
                LDMX4(aL[mt], A1 + ro);
            }
            // B: one x4 covers two adjacent n-tiles (b0,b1 each)
            uint32_t bH[2][4], bL[2][4];
#pragma unroll
            for (int np = 0; np < 2; ++np) {
                const uint32_t ro = (uint32_t)((wn * 32 + np * 16 + laneB_row) * XPADB
                                               + kb + laneB_koff);
                LDMX4(bH[np], B0 + ro);
                LDMX4(bL[np], B1 + ro);
            }
#pragma unroll
            for (int nt = 0; nt < 4; ++nt) {
                const uint32_t* bHv = &bH[nt >> 1][(nt & 1) * 2];
                const uint32_t* bLv = &bL[nt >> 1][(nt & 1) * 2];
#pragma unroll
                for (int mt = 0; mt < 4; ++mt) {
                    MMA_BF16(acc[mt][nt], aH[mt], bHv[0], bHv[1]);   // xh*wh
                    MMA_BF16(acc[mt][nt], aH[mt], bLv[0], bLv[1]);   // xh*wl
                    MMA_BF16(acc[mt][nt], aL[mt], bHv[0], bHv[1]);   // xl*wh
                }
            }
        }

        if (ch < 7) {
            asm volatile("cp.async.wait_group 0;" ::: "memory");
            __syncthreads();
        }
    }

    // Epilogue: fused bias, direct float2 stores
#pragma unroll
    for (int nt = 0; nt < 4; ++nt) {
        const int c = h0 + wn * 32 + nt * 8 + lc;
        const float bs0 = bih[c] + bhh[c];
        const float bs1 = bih[c + 1] + bhh[c + 1];
#pragma unroll
        for (int mt = 0; mt < 4; ++mt) {
            const int r = m0 + wm * 64 + mt * 16 + lr;
            float2 v0 = make_float2(acc[mt][nt][0] + bs0, acc[mt][nt][1] + bs1);
            float2 v1 = make_float2(acc[mt][nt][2] + bs0, acc[mt][nt][3] + bs1);
            *(float2*)(g_xproj + (size_t)r * Hdim + c) = v0;
            *(float2*)(g_xproj + (size_t)(r + 8) * Hdim + c) = v1;
        }
    }
}

// ---------------------------------------------------------------------------
// Kernel 2: the recurrence — all-to-all of M-partials via bulk DSMEM engine.
//   Round-9 structure with ONE change: the own chunk also goes through the
//   engine (uniform 8 copies, expect 8*512) so the barrier orders everything
//   and the second per-step __syncthreads is deleted. hloc double-buffered
//   (the hazard that syncthreads covered); all other buffers tolerate the
//   resulting ±1-step intra-CTA skew (slot-by-slot verified).
// ---------------------------------------------------------------------------
__global__ void __launch_bounds__(256, 1) __cluster_dims__(8, 1, 1)
rnn_kernel(const float* __restrict__ Whh,   // [512, 512]
           const float* __restrict__ kern,  // [4]
           float* __restrict__ out_states,  // [B, T, H]
           float* __restrict__ out_last)    // [B, H]
{
    __shared__ __align__(16) float arr[2][8][128];    // 8KB [slot][src][swz 512B]
    __shared__ __align__(16) float stg[2][8][128];    // 8KB [slot][warp][512B]
    __shared__ __align__(16) float hloc[2][2][64];    // [slot][batch][row]
    __shared__ __align__(16) float xs[2][2][8][64];   // 8KB xproj stage
    __shared__ __align__(16) float xout[2][2][8][64]; // 8KB output stage (dbuf)
    __shared__ __align__(8)  u64 mbars[2];

    const int tid   = threadIdx.x;
    const int lane  = tid & 31;
    const int w     = tid >> 5;            // warp id == destination peer
    const int slice = blockIdx.x;          // cluster rank 0..7
    const int grp   = blockIdx.y;          // 0..15
    const int b0    = grp * 2;

    u64 wR0[32], wR1[32];
    {
        const float* r0p = Whh + (size_t)(64 * w + 2 * lane) * Hdim + 64 * slice;
        const float* r1p = r0p + Hdim;
#pragma unroll
        for (int m = 0; m < 16; ++m) {
            ulonglong2 u0 = *(const ulonglong2*)(r0p + 4 * m);
            ulonglong2 u1 = *(const ulonglong2*)(r1p + 4 * m);
            wR0[2 * m] = u0.x; wR0[2 * m + 1] = u0.y;
            wR1[2 * m] = u1.x; wR1[2 * m + 1] = u1.y;
        }
    }
    const u64 kk0 = pk2(kern[0], kern[0]), kk1 = pk2(kern[1], kern[1]);
    const u64 kk2 = pk2(kern[2], kern[2]), kk3 = pk2(kern[3], kern[3]);

    // Tx-barriers: count 1, expect 8*512 B per slot (all 8 chunks via engine)
    const uint32_t mb0 = s2u(&mbars[0]);
    if (tid == 0) {
        mbar_init(mb0, 1);
        mbar_init(mb0 + 8, 1);
        mbar_arrive_expect_tx(mb0, 8 * 512);
        mbar_arrive_expect_tx(mb0 + 8, 8 * 512);
    }

    const uint32_t arr_b = s2u(arr);
    const uint32_t dst_b = mapa_rank(arr_b, w) + (uint32_t)(slice * 512);
    const uint32_t bar_b = mapa_rank(mb0, w);

    cluster_sync_asm();

    const int pb  = tid >> 7;
    const int pt  = (tid >> 4) & 7;
    const int pu  = tid & 15;
    const float* xsrc = g_xproj + (size_t)(b0 + pb) * Tlen * Hdim
                        + (size_t)pt * Hdim + slice * 64 + pu * 4;
    *(float4*)&xs[0][pb][pt][pu * 4] = *(const float4*)(xsrc);
    float4 xpre = *(const float4*)(xsrc + 8 * Hdim);
    __syncthreads();

    const int row  = tid >> 2;
    const int quad = tid & 3;

    u64 ring0 = 0ull, ring1 = 0ull, ring2 = 0ull;

    const char* arrc = (const char*)arr;

    for (int t = 0; t < Tlen; ++t) {
        // ---- Gap fillers BEFORE the wait ----
        if ((t & 7) == 0) {
            int g = t >> 3;
            *(float4*)&xs[(g + 1) & 1][pb][pt][pu * 4] = xpre;
            if (t + 16 < Tlen)
                xpre = *(const float4*)(xsrc + (size_t)(t + 16) * Hdim);
            if (t > 0) {
                *(float4*)(out_states + (size_t)(b0 + pb) * Tlen * Hdim
                           + (size_t)(t - 8 + pt) * Hdim + slice * 64 + pu * 4)
                    = *(const float4*)&xout[(g - 1) & 1][pb][pt][pu * 4];
            }
        }

        // ---- Phase A: wait, gather M_{t-1}, taps, tanh -> h_t ----
        u64 Mt1 = 0ull;
        if (t > 0) {
            const uint32_t bar = mb0 + ((t - 1) & 1) * 8;
            mbar_wait_parity(bar, ((t - 1) >> 1) & 1);
            if (tid == 0)
                mbar_arrive_expect_tx(bar, 8 * 512);

            const char* ab = arrc + ((t - 1) & 1) * 4096;
            const int s0 = 2 * quad, s1 = 2 * quad + 1;
            const int pbk = row >> 1, rb = (row & 1) * 8;
            u64 v0 = *(const u64*)(ab + s0 * 512 + (((pbk + 5 * s0) & 31) * 16 + rb));
            u64 v1 = *(const u64*)(ab + s1 * 512 + (((pbk + 5 * s1) & 31) * 16 + rb));
            u64 m = add2(v0, v1);
            m = add2(m, shflx2(m, 1));
            m = add2(m, shflx2(m, 2));
            Mt1 = m;
        }

        u64 rr = fma2(kk0, Mt1, fma2(kk1, ring0, fma2(kk2, ring1, mul2(kk3, ring2))));
        ring2 = ring1; ring1 = ring0; ring0 = Mt1;

        if (quad < 2) {
            float2 rf = upk2(rr);
            float pre = (quad == 0) ? rf.x : rf.y;
            float val = ftanh(pre + xs[(t >> 3) & 1][quad][t & 7][row]);
            hloc[t & 1][quad][row] = val;
            xout[(t >> 3) & 1][quad][t & 7][row] = val;
            if (t == Tlen - 1)
                out_last[(size_t)(b0 + quad) * Hdim + slice * 64 + row] = val;
        }

        __syncthreads();   // hloc/xout ready (single barrier per step)

        // ---- Phase B: per-warp partial chunk GEMV + engine send (all 8) ----
        if (t < Tlen - 1) {
            const float* hl0 = &hloc[t & 1][0][0];
            const float* hl1 = &hloc[t & 1][1][0];
            u64 aA0 = 0ull, cA0 = 0ull, aA1 = 0ull, cA1 = 0ull;
            u64 aB0 = 0ull, cB0 = 0ull, aB1 = 0ull, cB1 = 0ull;
#pragma unroll
            for (int m = 0; m < 16; ++m) {
                ulonglong2 h0 = *(const ulonglong2*)(hl0 + 4 * m);
                ulonglong2 h1 = *(const ulonglong2*)(hl1 + 4 * m);
                aA0 = fma2(wR0[2 * m],     h0.x, aA0);
                cA0 = fma2(wR0[2 * m + 1], h0.y, cA0);
                aA1 = fma2(wR0[2 * m],     h1.x, aA1);
                cA1 = fma2(wR0[2 * m + 1], h1.y, cA1);
                aB0 = fma2(wR1[2 * m],     h0.x, aB0);
                cB0 = fma2(wR1[2 * m + 1], h0.y, cB0);
                aB1 = fma2(wR1[2 * m],     h1.x, aB1);
                cB1 = fma2(wR1[2 * m + 1], h1.y, cB1);
            }
            float2 fA0 = upk2(add2(aA0, cA0));
            float2 fA1 = upk2(add2(aA1, cA1));
            float2 fB0 = upk2(add2(aB0, cB0));
            float2 fB1 = upk2(add2(aB1, cB1));
            float4 o = make_float4(fA0.x + fA0.y, fA1.x + fA1.y,
                                   fB0.x + fB0.y, fB1.x + fB1.y);
            float* dstp = &stg[t & 1][w][0];
            *(float4*)(dstp + ((lane + 5 * slice) & 31) * 4) = o;
            __syncwarp();
            if (lane == 0) {
                fence_proxy_async_cta();
                bulk_dsmem(dst_b + (uint32_t)((t & 1) * 4096),
                           s2u(&stg[t & 1][w][0]), 512,
                           bar_b + (uint32_t)((t & 1) * 8));
            }
        }
        // no second __syncthreads — barrier tx-accounting orders the exchange
    }

    // Final output group (t = 1016..1023, buffer 1)
    *(float4*)(out_states + (size_t)(b0 + pb) * Tlen * Hdim
               + (size_t)(Tlen - 8 + pt) * Hdim + slice * 64 + pu * 4)
        = *(const float4*)&xout[1][pb][pt][pu * 4];

    // No CTA may exit while peers' bulk copies could still target it
    cluster_sync_asm();
}

// ---------------------------------------------------------------------------
extern "C" void kernel_launch(void* const* d_in, const int* in_sizes, int n_in,
                              void* d_out, int out_size)
{
    (void)in_sizes; (void)n_in; (void)out_size;
    const float* x    = (const float*)d_in[0];   // [32, 1024, 512]
    const float* Wih  = (const float*)d_in[1];   // [512, 512]
    const float* Whh  = (const float*)d_in[2];   // [512, 512]
    const float* bih  = (const float*)d_in[3];   // [512]
    const float* bhh  = (const float*)d_in[4];   // [512]
    const float* kern = (const float*)d_in[5];   // [4]

    float* out        = (float*)d_out;
    float* out_states = out;                                   // [32,1024,512]
    float* out_last   = out + (size_t)Bsz * Tlen * Hdim;       // [32,512]

    // 0) Split X and Wih into bf16 hi/lo (single launch)
    int nx4 = (Bsz * Tlen * Idim) / 4;
    int nw4 = (Hdim * Idim) / 4;
    split_bf16_kernel<<<(nx4 + nw4 + 255) / 256, 256>>>(x, Wih, nx4, nx4 + nw4);

    // 1) Input projection on HMMA tensor cores (split-bf16, fp32 accumulate)
    cudaFuncSetAttribute(xproj_mma_kernel,
                         cudaFuncAttributeMaxDynamicSharedMemorySize, XS_TOTAL);
    dim3 gx(Hdim / 128, (Bsz * Tlen) / 128);   // (4, 256)
    xproj_mma_kernel<<<gx, 256, XS_TOTAL>>>(bih, bhh);

    // 2) Sequential recurrence: 16 clusters of 8 CTAs
    dim3 gr(8, 16);
    rnn_kernel<<<gr, 256>>>(Whh, kern, out_states, out_last);
}

// round 17
// speedup vs baseline: 1.0470x; 1.0470x over previous
#include <cuda_runtime.h>
#include <cuda_bf16.h>
#include <cstdint>

// Problem constants
#define Bsz 32
#define Tlen 1024
#define Idim 512
#define Hdim 512

// Scratch (device globals: no allocation allowed)
__device__ float g_xproj[(size_t)Bsz * Tlen * Hdim];                  // 64 MB
__device__ __align__(16) __nv_bfloat16 g_xh[(size_t)Bsz * Tlen * Idim];
__device__ __align__(16) __nv_bfloat16 g_xl[(size_t)Bsz * Tlen * Idim];
__device__ __align__(16) __nv_bfloat16 g_wh[(size_t)Hdim * Idim];
__device__ __align__(16) __nv_bfloat16 g_wl[(size_t)Hdim * Idim];

// ---------------------------------------------------------------------------
// packed f32x2 helpers (FFMA2 — ptxas never auto-fuses; PTX-only)
// ---------------------------------------------------------------------------
using u64 = unsigned long long;
__device__ __forceinline__ u64 pk2(float lo, float hi) {
    u64 r; asm("mov.b64 %0,{%1,%2};" : "=l"(r) : "f"(lo), "f"(hi)); return r;
}
__device__ __forceinline__ float2 upk2(u64 v) {
    float2 f; asm("mov.b64 {%0,%1},%2;" : "=f"(f.x), "=f"(f.y) : "l"(v)); return f;
}
__device__ __forceinline__ u64 fma2(u64 a, u64 b, u64 c) {
    u64 d; asm("fma.rn.f32x2 %0,%1,%2,%3;" : "=l"(d) : "l"(a), "l"(b), "l"(c)); return d;
}
__device__ __forceinline__ u64 add2(u64 a, u64 b) {
    u64 d; asm("add.rn.f32x2 %0,%1,%2;" : "=l"(d) : "l"(a), "l"(b)); return d;
}
__device__ __forceinline__ u64 mul2(u64 a, u64 b) {
    u64 d; asm("mul.rn.f32x2 %0,%1,%2;" : "=l"(d) : "l"(a), "l"(b)); return d;
}

__device__ __forceinline__ uint32_t s2u(const void* p) {
    uint32_t a;
    asm("{ .reg .u64 t; cvta.to.shared.u64 t, %1; cvt.u32.u64 %0, t; }"
        : "=r"(a) : "l"(p));
    return a;
}
__device__ __forceinline__ uint32_t mapa_rank(uint32_t laddr, uint32_t rank) {
    uint32_t r;
    asm("mapa.shared::cluster.u32 %0, %1, %2;" : "=r"(r) : "r"(laddr), "r"(rank));
    return r;
}
__device__ __forceinline__ void mbar_init(uint32_t mb, uint32_t cnt) {
    asm volatile("mbarrier.init.shared.b64 [%0], %1;" :: "r"(mb), "r"(cnt) : "memory");
}
__device__ __forceinline__ void mbar_arrive_expect_tx(uint32_t mb, uint32_t bytes) {
    asm volatile("mbarrier.arrive.expect_tx.shared.b64 _, [%0], %1;"
                 :: "r"(mb), "r"(bytes) : "memory");
}
__device__ __forceinline__ void mbar_wait_parity(uint32_t mb, uint32_t parity) {
    asm volatile(
        "{\n\t"
        ".reg .pred P;\n\t"
        "WLOOP_%=:\n\t"
        "mbarrier.try_wait.parity.acquire.cta.shared::cta.b64 P, [%0], %1, 0x989680;\n\t"
        "@P bra.uni WDONE_%=;\n\t"
        "bra.uni WLOOP_%=;\n\t"
        "WDONE_%=:\n\t"
        "}"
        :: "r"(mb), "r"(parity) : "memory");
}
__device__ __forceinline__ void bulk_dsmem(uint32_t dst, uint32_t src,
                                           uint32_t bytes, uint32_t rembar) {
    asm volatile(
        "cp.async.bulk.shared::cluster.shared::cta.mbarrier::complete_tx::bytes "
        "[%0], [%1], %2, [%3];"
        :: "r"(dst), "r"(src), "r"(bytes), "r"(rembar) : "memory");
}
__device__ __forceinline__ void fence_proxy_async_cta() {
    asm volatile("fence.proxy.async.shared::cta;" ::: "memory");
}
__device__ __forceinline__ void cluster_sync_asm() {
    asm volatile("barrier.cluster.arrive.aligned;" ::: "memory");
    asm volatile("barrier.cluster.wait.aligned;" ::: "memory");
}
__device__ __forceinline__ u64 shflx2(u64 v, int m) {
    float2 f = upk2(v);
    f.x = __shfl_xor_sync(0xFFFFFFFFu, f.x, m);
    f.y = __shfl_xor_sync(0xFFFFFFFFu, f.y, m);
    return pk2(f.x, f.y);
}
// Fast branch-free tanh (rel err ~1e-6, fine vs 1e-3 tolerance)
__device__ __forceinline__ float ftanh(float x) {
    float ax = fabsf(x);
    float e = __expf(-2.0f * ax);
    float r = __fdividef(1.0f - e, 1.0f + e);
    return copysignf(r, x);
}

// ---------------------------------------------------------------------------
// Kernel 0: split fp32 -> (bf16 hi, bf16 lo). One launch covers X then Wih.
//   2 elements per thread via grid-stride halves (both sweeps coalesced).
// ---------------------------------------------------------------------------
__device__ __forceinline__ void split_one(const float* __restrict__ x,
                                          const float* __restrict__ wih,
                                          int nx4, int i)
{
    const float* src;
    __nv_bfloat16 *hi, *lo;
    int j;
    if (i < nx4) { src = x;   hi = g_xh; lo = g_xl; j = i; }
    else         { src = wih; hi = g_wh; lo = g_wl; j = i - nx4; }
    float4 v = ((const float4*)src)[j];
    __nv_bfloat16 h0 = __float2bfloat16(v.x);
    __nv_bfloat16 h1 = __float2bfloat16(v.y);
    __nv_bfloat16 h2 = __float2bfloat16(v.z);
    __nv_bfloat16 h3 = __float2bfloat16(v.w);
    __nv_bfloat16 l0 = __float2bfloat16(v.x - __bfloat162float(h0));
    __nv_bfloat16 l1 = __float2bfloat16(v.y - __bfloat162float(h1));
    __nv_bfloat16 l2 = __float2bfloat16(v.z - __bfloat162float(h2));
    __nv_bfloat16 l3 = __float2bfloat16(v.w - __bfloat162float(h3));
    __nv_bfloat162* hp = (__nv_bfloat162*)(hi + 4 * (size_t)j);
    __nv_bfloat162* lp = (__nv_bfloat162*)(lo + 4 * (size_t)j);
    hp[0] = __halves2bfloat162(h0, h1);
    hp[1] = __halves2bfloat162(h2, h3);
    lp[0] = __halves2bfloat162(l0, l1);
    lp[1] = __halves2bfloat162(l2, l3);
}

__global__ void split_bf16_kernel(const float* __restrict__ x,
                                  const float* __restrict__ wih,
                                  int nx4, int ntot4, int half)
{
    int i = blockIdx.x * blockDim.x + threadIdx.x;
    if (i < half) split_one(x, wih, nx4, i);
    int i2 = i + half;
    if (i2 < ntot4) split_one(x, wih, nx4, i2);
}

// ---------------------------------------------------------------------------
// Kernel 1: xproj via mma.sync.m16n8k16.bf16 (split-bf16, 3-product fp32
//   emulation; HMMA — tcgen05 unavailable through compute_103 PTX).
//   CTA tile 128m x 128n, K chunked by 64, cp.async double-buffered smem,
//   pad-72 rows => all fragment loads bank-conflict-free.
// ---------------------------------------------------------------------------
#define MMA_BF16(d, a, b0_, b1_) \
    asm volatile( \
        "mma.sync.aligned.m16n8k16.row.col.f32.bf16.bf16.f32 " \
        "{%0,%1,%2,%3}, {%4,%5,%6,%7}, {%8,%9}, {%0,%1,%2,%3};" \
        : "+f"((d)[0]), "+f"((d)[1]), "+f"((d)[2]), "+f"((d)[3]) \
        : "r"((a)[0]), "r"((a)[1]), "r"((a)[2]), "r"((a)[3]), \
          "r"(b0_), "r"(b1_))

static constexpr int XPADB = 144;                   // 72 bf16 per row, bytes
static constexpr int MAT_BYTES = 128 * XPADB;       // 18432
static constexpr int BUF_BYTES = 4 * MAT_BYTES;     // 73728
static constexpr int XS_TOTAL  = 2 * BUF_BYTES;     // 147456

__global__ void __launch_bounds__(256, 1)
xproj_mma_kernel(const float* __restrict__ bih, const float* __restrict__ bhh)
{
    extern __shared__ __align__(128) char xsm[];
    const int tid  = threadIdx.x;
    const int lane = tid & 31;
    const int w    = tid >> 5;
    const int wm   = w >> 2;          // 0..1 (m 64-block)
    const int wn   = w & 3;           // 0..3 (n 32-block)
    const int m0 = blockIdx.y * 128;
    const int h0 = blockIdx.x * 128;
    const uint32_t sb = s2u(xsm);

    const int lr = lane >> 2;         // fragment row 0..7
    const int lc = (lane & 3) * 2;    // fragment k/col pair base

    auto issue_chunk = [&](int buf, int k0) {
#pragma unroll
        for (int q = 0; q < 16; ++q) {
            int idx = tid + 256 * q;
            int mat = idx >> 10;          // 0=xh 1=xl 2=wh 3=wl
            int it  = idx & 1023;
            int r   = it >> 3;
            int c8  = (it & 7) * 8;
            const __nv_bfloat16* src;
            if (mat == 0)      src = g_xh + (size_t)(m0 + r) * Idim + k0 + c8;
            else if (mat == 1) src = g_xl + (size_t)(m0 + r) * Idim + k0 + c8;
            else if (mat == 2) src = g_wh + (size_t)(h0 + r) * Idim + k0 + c8;
            else               src = g_wl + (size_t)(h0 + r) * Idim + k0 + c8;
            uint32_t dst = sb + (uint32_t)(buf * BUF_BYTES + mat * MAT_BYTES
                                           + r * XPADB + c8 * 2);
            asm volatile("cp.async.cg.shared.global [%0], [%1], 16;"
                         :: "r"(dst), "l"(src));
        }
        asm volatile("cp.async.commit_group;" ::: "memory");
    };

    issue_chunk(0, 0);

    float acc[4][4][4];
#pragma unroll
    for (int i = 0; i < 4; ++i)
#pragma unroll
        for (int j = 0; j < 4; ++j)
#pragma unroll
            for (int v = 0; v < 4; ++v) acc[i][j][v] = 0.f;

    asm volatile("cp.async.wait_group 0;" ::: "memory");
    __syncthreads();

    for (int ch = 0; ch < 8; ++ch) {
        const int buf = ch & 1;
        if (ch < 7) issue_chunk(buf ^ 1, (ch + 1) * 64);

        const char* A0 = xsm + buf * BUF_BYTES;        // xh
        const char* A1 = A0 + MAT_BYTES;               // xl
        const char* B0 = A0 + 2 * MAT_BYTES;           // wh
        const char* B1 = A0 + 3 * MAT_BYTES;           // wl

#pragma unroll
        for (int kk = 0; kk < 4; ++kk) {
            const int kb2 = (kk * 16 + lc) * 2;        // byte offset in row
            uint32_t aH[4][4], aL[4][4];
#pragma unroll
            for (int mt = 0; mt < 4; ++mt) {
                const int rb = wm * 64 + mt * 16 + lr;
                const char* pH = A0 + rb * XPADB + kb2;
                const char* pL = A1 + rb * XPADB + kb2;
                aH[mt][0] = *(const uint32_t*)(pH);
                aH[mt][1] = *(const uint32_t*)(pH + 8 * XPADB);
                aH[mt][2] = *(const uint32_t*)(pH + 16);
                aH[mt][3] = *(const uint32_t*)(pH + 8 * XPADB + 16);
                aL[mt][0] = *(const uint32_t*)(pL);
                aL[mt][1] = *(const uint32_t*)(pL + 8 * XPADB);
                aL[mt][2] = *(const uint32_t*)(pL + 16);
                aL[mt][3] = *(const uint32_t*)(pL + 8 * XPADB + 16);
            }
#pragma unroll
            for (int nt = 0; nt < 4; ++nt) {
                const int hb = wn * 32 + nt * 8 + lr;
                const char* qH = B0 + hb * XPADB + kb2;
                const char* qL = B1 + hb * XPADB + kb2;
                uint32_t bH0 = *(const uint32_t*)(qH);
                uint32_t bH1 = *(const uint32_t*)(qH + 16);
                uint32_t bL0 = *(const uint32_t*)(qL);
                uint32_t bL1 = *(const uint32_t*)(qL + 16);
#pragma unroll
                for (int mt = 0; mt < 4; ++mt) {
                    MMA_BF16(acc[mt][nt], aH[mt], bH0, bH1);   // xh*wh
                    MMA_BF16(acc[mt][nt], aH[mt], bL0, bL1);   // xh*wl
                    MMA_BF16(acc[mt][nt], aL[mt], bH0, bH1);   // xl*wh
                }
            }
        }

        if (ch < 7) {
            asm volatile("cp.async.wait_group 0;" ::: "memory");
            __syncthreads();
        }
    }

    // Epilogue: fused bias, direct float2 stores (32B-sector aligned)
#pragma unroll
    for (int nt = 0; nt < 4; ++nt) {
        const int c = h0 + wn * 32 + nt * 8 + lc;
        const float bs0 = __ldg(bih + c) + __ldg(bhh + c);
        const float bs1 = __ldg(bih + c + 1) + __ldg(bhh + c + 1);
#pragma unroll
        for (int mt = 0; mt < 4; ++mt) {
            const int r = m0 + wm * 64 + mt * 16 + lr;
            float2 v0 = make_float2(acc[mt][nt][0] + bs0, acc[mt][nt][1] + bs1);
            float2 v1 = make_float2(acc[mt][nt][2] + bs0, acc[mt][nt][3] + bs1);
            *(float2*)(g_xproj + (size_t)r * Hdim + c) = v0;
            *(float2*)(g_xproj + (size_t)(r + 8) * Hdim + c) = v1;
        }
    }
}

// ---------------------------------------------------------------------------
// Kernel 2: the recurrence — all-to-all of M-partials via bulk DSMEM engine.
//   Round-14 structure (measured best) with ONE scheduling tweak: the
//   out_states flush moved from the (t&7)==0 gap to the (t&7)==4 gap, so the
//   every-8-step burst (xs STS + prefetch LDG + output STG) is spread over
//   two fabric gaps instead of one. Same buffers, same ordering guarantees.
// ---------------------------------------------------------------------------
__global__ void __launch_bounds__(256, 1) __cluster_dims__(8, 1, 1)
rnn_kernel(const float* __restrict__ Whh,   // [512, 512]
           const float* __restrict__ kern,  // [4]
           float* __restrict__ out_states,  // [B, T, H]
           float* __restrict__ out_last)    // [B, H]
{
    __shared__ __align__(16) float arr[2][8][128];    // 8KB [slot][src][swz 512B]
    __shared__ __align__(16) float stg[2][8][128];    // 8KB [slot][warp][512B]
    __shared__ __align__(16) float hloc[2][64];       // h_t[own rows], batch-major
    __shared__ __align__(16) float xs[2][2][8][64];   // 8KB xproj stage
    __shared__ __align__(16) float xout[2][2][8][64]; // 8KB output stage (dbuf)
    __shared__ __align__(8)  u64 mbars[2];

    const int tid   = threadIdx.x;
    const int lane  = tid & 31;
    const int w     = tid >> 5;            // warp id == destination peer
    const int slice = blockIdx.x;          // cluster rank 0..7
    const int grp   = blockIdx.y;          // 0..15
    const int b0    = grp * 2;

    u64 wR0[32], wR1[32];
    {
        const float* r0p = Whh + (size_t)(64 * w + 2 * lane) * Hdim + 64 * slice;
        const float* r1p = r0p + Hdim;
#pragma unroll
        for (int m = 0; m < 16; ++m) {
            ulonglong2 u0 = *(const ulonglong2*)(r0p + 4 * m);
            ulonglong2 u1 = *(const ulonglong2*)(r1p + 4 * m);
            wR0[2 * m] = u0.x; wR0[2 * m + 1] = u0.y;
            wR1[2 * m] = u1.x; wR1[2 * m + 1] = u1.y;
        }
    }
    const u64 kk0 = pk2(kern[0], kern[0]), kk1 = pk2(kern[1], kern[1]);
    const u64 kk2 = pk2(kern[2], kern[2]), kk3 = pk2(kern[3], kern[3]);

    const uint32_t mb0 = s2u(&mbars[0]);
    if (tid == 0) {
        mbar_init(mb0, 1);
        mbar_init(mb0 + 8, 1);
        mbar_arrive_expect_tx(mb0, 7 * 512);
        mbar_arrive_expect_tx(mb0 + 8, 7 * 512);
    }

    const uint32_t arr_b = s2u(arr);
    const uint32_t dst_b = mapa_rank(arr_b, w) + (uint32_t)(slice * 512);
    const uint32_t bar_b = mapa_rank(mb0, w);

    cluster_sync_asm();

    const int pb  = tid >> 7;
    const int pt  = (tid >> 4) & 7;
    const int pu  = tid & 15;
    const float* xsrc = g_xproj + (size_t)(b0 + pb) * Tlen * Hdim
                        + (size_t)pt * Hdim + slice * 64 + pu * 4;
    *(float4*)&xs[0][pb][pt][pu * 4] = *(const float4*)(xsrc);
    float4 xpre = *(const float4*)(xsrc + 8 * Hdim);
    __syncthreads();

    const int row  = tid >> 2;
    const int quad = tid & 3;

    u64 ring0 = 0ull, ring1 = 0ull, ring2 = 0ull;

    const char* arrc = (const char*)arr;

    for (int t = 0; t < Tlen; ++t) {
        // ---- Gap fillers BEFORE the wait (split over two gaps) ----
        if ((t & 7) == 0) {
            int g = t >> 3;
            *(float4*)&xs[(g + 1) & 1][pb][pt][pu * 4] = xpre;
            if (t + 16 < Tlen)
                xpre = *(const float4*)(xsrc + (size_t)(t + 16) * Hdim);
        } else if ((t & 7) == 4 && t > 4) {
            // Flush group g-1 (complete since step t-5; buffer not rewritten
            // until t+4; per-step barriers give cross-thread visibility)
            int g = t >> 3;
            *(float4*)(out_states + (size_t)(b0 + pb) * Tlen * Hdim
                       + (size_t)(t - 12 + pt) * Hdim + slice * 64 + pu * 4)
                = *(const float4*)&xout[(g - 1) & 1][pb][pt][pu * 4];
        }

        // ---- Phase A: wait, gather M_{t-1}, taps, tanh -> h_t ----
        u64 Mt1 = 0ull;
        if (t > 0) {
            const uint32_t bar = mb0 + ((t - 1) & 1) * 8;
            mbar_wait_parity(bar, ((t - 1) >> 1) & 1);
            if (tid == 0)
                mbar_arrive_expect_tx(bar, 7 * 512);

            const char* ab = arrc + ((t - 1) & 1) * 4096;
            const int s0 = 2 * quad, s1 = 2 * quad + 1;
            const int pbk = row >> 1, rb = (row & 1) * 8;
            u64 v0 = *(const u64*)(ab + s0 * 512 + (((pbk + 5 * s0) & 31) * 16 + rb));
            u64 v1 = *(const u64*)(ab + s1 * 512 + (((pbk + 5 * s1) & 31) * 16 + rb));
            u64 m = add2(v0, v1);
            m = add2(m, shflx2(m, 1));
            m = add2(m, shflx2(m, 2));
            Mt1 = m;
        }

        u64 rr = fma2(kk0, Mt1, fma2(kk1, ring0, fma2(kk2, ring1, mul2(kk3, ring2))));
        ring2 = ring1; ring1 = ring0; ring0 = Mt1;

        if (quad < 2) {
            float2 rf = upk2(rr);
            float pre = (quad == 0) ? rf.x : rf.y;
            float val = ftanh(pre + xs[(t >> 3) & 1][quad][t & 7][row]);
            hloc[quad][row] = val;
            xout[(t >> 3) & 1][quad][t & 7][row] = val;
            if (t == Tlen - 1)
                out_last[(size_t)(b0 + quad) * Hdim + slice * 64 + row] = val;
        }

        __syncthreads();

        // ---- Phase B: per-warp partial chunk GEMV + immediate send ----
        if (t < Tlen - 1) {
            u64 aA0 = 0ull, cA0 = 0ull, aA1 = 0ull, cA1 = 0ull;
            u64 aB0 = 0ull, cB0 = 0ull, aB1 = 0ull, cB1 = 0ull;
#pragma unroll
            for (int m = 0; m < 16; ++m) {
                ulonglong2 h0 = *(const ulonglong2*)&hloc[0][4 * m];
                ulonglong2 h1 = *(const ulonglong2*)&hloc[1][4 * m];
                aA0 = fma2(wR0[2 * m],     h0.x, aA0);
                cA0 = fma2(wR0[2 * m + 1], h0.y, cA0);
                aA1 = fma2(wR0[2 * m],     h1.x, aA1);
                cA1 = fma2(wR0[2 * m + 1], h1.y, cA1);
                aB0 = fma2(wR1[2 * m],     h0.x, aB0);
                cB0 = fma2(wR1[2 * m + 1], h0.y, cB0);
                aB1 = fma2(wR1[2 * m],     h1.x, aB1);
                cB1 = fma2(wR1[2 * m + 1], h1.y, cB1);
            }
            float2 fA0 = upk2(add2(aA0, cA0));
            float2 fA1 = upk2(add2(aA1, cA1));
            float2 fB0 = upk2(add2(aB0, cB0));
            float2 fB1 = upk2(add2(aB1, cB1));
            float4 o = make_float4(fA0.x + fA0.y, fA1.x + fA1.y,
                                   fB0.x + fB0.y, fB1.x + fB1.y);
            float* dstp = (w == slice) ? &arr[t & 1][slice][0]
                                       : &stg[t & 1][w][0];
            *(float4*)(dstp + ((lane + 5 * slice) & 31) * 4) = o;
            __syncwarp();
            if (w != slice && lane == 0) {
                fence_proxy_async_cta();
                bulk_dsmem(dst_b + (uint32_t)((t & 1) * 4096),
                           s2u(&stg[t & 1][w][0]), 512,
                           bar_b + (uint32_t)((t & 1) * 8));
            }
        }

        __syncthreads();   // own-chunk STS visible to next step's gather
    }

    // Final output group (t = 1016..1023, buffer 1)
    *(float4*)(out_states + (size_t)(b0 + pb) * Tlen * Hdim
               + (size_t)(Tlen - 8 + pt) * Hdim + slice * 64 + pu * 4)
        = *(const float4*)&xout[1][pb][pt][pu * 4];

    // No CTA may exit while peers' bulk copies could still target it
    cluster_sync_asm();
}

// ---------------------------------------------------------------------------
extern "C" void kernel_launch(void* const* d_in, const int* in_sizes, int n_in,
                              void* d_out, int out_size)
{
    (void)in_sizes; (void)n_in; (void)out_size;
    const float* x    = (const float*)d_in[0];   // [32, 1024, 512]
    const float* Wih  = (const float*)d_in[1];   // [512, 512]
    const float* Whh  = (const float*)d_in[2];   // [512, 512]
    const float* bih  = (const float*)d_in[3];   // [512]
    const float* bhh  = (const float*)d_in[4];   // [512]
    const float* kern = (const float*)d_in[5];   // [4]

    float* out        = (float*)d_out;
    float* out_states = out;                                   // [32,1024,512]
    float* out_last   = out + (size_t)Bsz * Tlen * Hdim;       // [32,512]

    // 0) Split X and Wih into bf16 hi/lo (single launch, 2 elems/thread)
    int nx4 = (Bsz * Tlen * Idim) / 4;
    int nw4 = (Hdim * Idim) / 4;
    int ntot4 = nx4 + nw4;
    int half = (ntot4 + 1) / 2;
    split_bf16_kernel<<<(half + 255) / 256, 256>>>(x, Wih, nx4, ntot4, half);

    // 1) Input projection on HMMA tensor cores (split-bf16, fp32 accumulate)
    cudaFuncSetAttribute(xproj_mma_kernel,
                         cudaFuncAttributeMaxDynamicSharedMemorySize, XS_TOTAL);
    dim3 gx(Hdim / 128, (Bsz * Tlen) / 128);   // (4, 256)
    xproj_mma_kernel<<<gx, 256, XS_TOTAL>>>(bih, bhh);

    // 2) Sequential recurrence: 16 clusters of 8 CTAs
    dim3 gr(8, 16);
    rnn_kernel<<<gr, 256>>>(Whh, kern, out_states, out_last);
}